// round 1
// baseline (speedup 1.0000x reference)
#include <cuda_runtime.h>
#include <math.h>

#define BATCH 4
#define CH 256
#define NSP 4096            // h*w = 64*64
#define GROUPS 8
#define CPG 32              // channels per group
#define GELEMS (CPG*NSP)    // 131072 elements per (b, group)
#define EPS 1e-5f

// ---------------- scratch (device globals; no allocation allowed) ----------------
__device__ float g_xn[BATCH*CH*NSP];        // groupnorm output            16.8 MB
__device__ float g_qkv[BATCH*3*CH*NSP];     // qkv conv output [b][o][p]   50.3 MB
__device__ float g_vT[BATCH*NSP*CH];        // V transposed   [b][p][c]    16.8 MB
__device__ float g_attn[BATCH*NSP*CH];      // attn output    [b][p][c]    16.8 MB
__device__ float g_gnpart[BATCH*GROUPS*8*2];

// ---------------- GroupNorm: partial reduction ----------------
__global__ void gn_partial(const float* __restrict__ x) {
    int blk = blockIdx.x;          // 32 (b,g) * 8 slices
    int bg = blk >> 3, slice = blk & 7;
    const float4* p4 = (const float4*)(x + bg*GELEMS + slice*(GELEMS/8));
    float s = 0.f, sq = 0.f;
    for (int i = threadIdx.x; i < GELEMS/8/4; i += 256) {
        float4 v = p4[i];
        s  += v.x + v.y + v.z + v.w;
        sq += v.x*v.x + v.y*v.y + v.z*v.z + v.w*v.w;
    }
    __shared__ float ss[256], ssq[256];
    ss[threadIdx.x] = s; ssq[threadIdx.x] = sq;
    __syncthreads();
    for (int st = 128; st > 0; st >>= 1) {
        if (threadIdx.x < st) {
            ss[threadIdx.x]  += ss[threadIdx.x + st];
            ssq[threadIdx.x] += ssq[threadIdx.x + st];
        }
        __syncthreads();
    }
    if (threadIdx.x == 0) {
        g_gnpart[blk*2 + 0] = ss[0];
        g_gnpart[blk*2 + 1] = ssq[0];
    }
}

// ---------------- GroupNorm: apply ----------------
__global__ void gn_apply(const float* __restrict__ x,
                         const float* __restrict__ gamma,
                         const float* __restrict__ beta) {
    int gi = blockIdx.x * 256 + threadIdx.x;     // float4 index
    int bg = gi >> 15;                            // (b,g) index   (GELEMS/4 = 32768)
    int c  = (gi >> 10) & (CH - 1);               // channel       (NSP/4 = 1024)
    float s = 0.f, sq = 0.f;
#pragma unroll
    for (int k = 0; k < 8; k++) {
        s  += g_gnpart[(bg*8 + k)*2 + 0];
        sq += g_gnpart[(bg*8 + k)*2 + 1];
    }
    float mean = s * (1.0f / GELEMS);
    float var  = sq * (1.0f / GELEMS) - mean * mean;
    float rstd = rsqrtf(var + EPS);
    float ga = gamma[c] * rstd;
    float be = beta[c] - mean * ga;
    float4 v = ((const float4*)x)[gi];
    float4 o;
    o.x = v.x*ga + be; o.y = v.y*ga + be; o.z = v.z*ga + be; o.w = v.w*ga + be;
    ((float4*)g_xn)[gi] = o;
}

// ---------------- Generic 64x64 tiled SGEMM ----------------
// C[b][m][n] = sum_k A[m][k] * B[...] + bias[m] (+ Res[b][m][n])
// BT=0: B is [K][N] per batch.  BT=1: B is [N][K] per batch.
template<int BT>
__global__ __launch_bounds__(256) void gemm64(
    const float* __restrict__ A, const float* __restrict__ Bg,
    const float* __restrict__ bias, const float* __restrict__ Res,
    float* __restrict__ Cg, int M, int N, int K,
    int strideB, int strideC, int strideR)
{
    __shared__ float As[16][68];
    __shared__ float Bs[16][68];
    int t = threadIdx.x;
    int tx = t & 15, ty = t >> 4;
    int n0 = blockIdx.x * 64, m0 = blockIdx.y * 64, b = blockIdx.z;
    const float* B = Bg + b * strideB;
    float* C = Cg + b * strideC;

    float acc[4][4] = {};
    int amm = t >> 2, ak4 = t & 3;      // A transpose-load mapping
    int bkk = t >> 4, bn4 = t & 15;     // BT=0 mapping
    int bnn = t >> 2, bk4 = t & 3;      // BT=1 mapping

    for (int k0 = 0; k0 < K; k0 += 16) {
        float4 av = *(const float4*)&A[(m0 + amm)*K + k0 + ak4*4];
        As[ak4*4+0][amm] = av.x; As[ak4*4+1][amm] = av.y;
        As[ak4*4+2][amm] = av.z; As[ak4*4+3][amm] = av.w;
        if (BT == 0) {
            float4 bv = *(const float4*)&B[(k0 + bkk)*N + n0 + bn4*4];
            *(float4*)&Bs[bkk][bn4*4] = bv;
        } else {
            float4 bv = *(const float4*)&B[(n0 + bnn)*K + k0 + bk4*4];
            Bs[bk4*4+0][bnn] = bv.x; Bs[bk4*4+1][bnn] = bv.y;
            Bs[bk4*4+2][bnn] = bv.z; Bs[bk4*4+3][bnn] = bv.w;
        }
        __syncthreads();
#pragma unroll
        for (int kk = 0; kk < 16; kk++) {
            float a[4], bv[4];
            *(float4*)a  = *(const float4*)&As[kk][ty*4];
            *(float4*)bv = *(const float4*)&Bs[kk][tx*4];
#pragma unroll
            for (int i = 0; i < 4; i++)
#pragma unroll
                for (int j = 0; j < 4; j++)
                    acc[i][j] += a[i] * bv[j];
        }
        __syncthreads();
    }

#pragma unroll
    for (int i = 0; i < 4; i++) {
        int m = m0 + ty*4 + i;
        float bi = bias[m];
        int off = m * N + n0 + tx*4;
        float4 o;
        o.x = acc[i][0] + bi; o.y = acc[i][1] + bi;
        o.z = acc[i][2] + bi; o.w = acc[i][3] + bi;
        if (Res) {
            float4 r = *(const float4*)&Res[b*strideR + off];
            o.x += r.x; o.y += r.y; o.z += r.z; o.w += r.w;
        }
        *(float4*)&C[off] = o;
    }
}

// ---------------- V transpose: [b][c][p] -> [b][p][c] ----------------
__global__ void transposeV(const float* __restrict__ qkv, float* __restrict__ vT) {
    __shared__ float tile[32][33];
    int b = blockIdx.z;
    int p0 = blockIdx.x * 32, c0 = blockIdx.y * 32;
    const float* V = qkv + (b*3*CH + 2*CH)*NSP;   // V section (channels 512..767)
    int tx = threadIdx.x, ty = threadIdx.y;       // 32 x 8
    for (int cc = ty; cc < 32; cc += 8)
        tile[cc][tx] = V[(c0 + cc)*NSP + p0 + tx];
    __syncthreads();
    for (int pp = ty; pp < 32; pp += 8)
        vT[(b*NSP + p0 + pp)*CH + c0 + tx] = tile[tx][pp];
}

// ---------------- Flash attention: BM=BN=64, c=256, online softmax ----------------
__global__ __launch_bounds__(256) void flash64(const float* __restrict__ qkv,
                                               const float* __restrict__ vT,
                                               float* __restrict__ out) {
    extern __shared__ float sm[];
    float* Qs  = sm;                 // [256][64]  (kc-major)
    float* Ks  = Qs + 256*64;        // [256][64]
    float* Vs  = Ks + 256*64;        // [64][260]  (j-major, padded)
    float* Ps  = Vs + 64*260;        // [64][68]
    float* mrow = Ps + 64*68;        // [64]
    float* lrow = mrow + 64;         // [64]
    float* arow = lrow + 64;         // [64]

    int t = threadIdx.x;
    int tx = t & 15, ty = t >> 4;
    int i0 = blockIdx.x * 64;
    int b  = blockIdx.y;
    const float* Qg = qkv + b*3*CH*NSP;          // channels 0..255
    const float* Kg = Qg + CH*NSP;               // channels 256..511
    const float* Vg = vT + b*NSP*CH;             // [p][c]

    // load Q tile (resident for entire CTA)
#pragma unroll
    for (int it = 0; it < 16; it++) {
        int task = it*256 + t;
        int kc = task >> 4, i4 = task & 15;
        float4 v = *(const float4*)&Qg[kc*NSP + i0 + i4*4];
        *(float4*)&Qs[kc*64 + i4*4] = v;
    }
    if (t < 64) { mrow[t] = -INFINITY; lrow[t] = 0.f; }

    float O[4][4][4];   // [ri][q][cc] -> channel = q*64 + tx*4 + cc
#pragma unroll
    for (int ri = 0; ri < 4; ri++)
#pragma unroll
        for (int q = 0; q < 4; q++)
#pragma unroll
            for (int cc = 0; cc < 4; cc++) O[ri][q][cc] = 0.f;
    __syncthreads();

    const float scale = 0.0625f;    // 1/sqrt(256)

    for (int j0 = 0; j0 < NSP; j0 += 64) {
        // load K tile [kc][j] and V tile [j][c]
#pragma unroll
        for (int it = 0; it < 16; it++) {
            int task = it*256 + t;
            int kc = task >> 4, j4 = task & 15;
            float4 v = *(const float4*)&Kg[kc*NSP + j0 + j4*4];
            *(float4*)&Ks[kc*64 + j4*4] = v;
        }
#pragma unroll
        for (int it = 0; it < 16; it++) {
            int task = it*256 + t;
            int j = task >> 6, c4 = task & 63;
            float4 v = *(const float4*)&Vg[(j0 + j)*CH + c4*4];
            *(float4*)&Vs[j*260 + c4*4] = v;
        }
        __syncthreads();

        // S = scale * Q^T K, 4x4 per thread
        float acc[4][4] = {};
#pragma unroll 8
        for (int kc = 0; kc < 256; kc++) {
            float a[4], bv[4];
            *(float4*)a  = *(const float4*)&Qs[kc*64 + ty*4];
            *(float4*)bv = *(const float4*)&Ks[kc*64 + tx*4];
#pragma unroll
            for (int i = 0; i < 4; i++)
#pragma unroll
                for (int j = 0; j < 4; j++)
                    acc[i][j] += a[i] * bv[j];
        }

        // online softmax update (row group = 16 lanes of one warp)
        float mnew[4], alv[4], rsum[4], mold[4];
#pragma unroll
        for (int ri = 0; ri < 4; ri++) {
#pragma unroll
            for (int cj = 0; cj < 4; cj++) acc[ri][cj] *= scale;
            float ml = fmaxf(fmaxf(acc[ri][0], acc[ri][1]),
                             fmaxf(acc[ri][2], acc[ri][3]));
            ml = fmaxf(ml, __shfl_xor_sync(0xffffffffu, ml, 8));
            ml = fmaxf(ml, __shfl_xor_sync(0xffffffffu, ml, 4));
            ml = fmaxf(ml, __shfl_xor_sync(0xffffffffu, ml, 2));
            ml = fmaxf(ml, __shfl_xor_sync(0xffffffffu, ml, 1));
            mold[ri] = mrow[ty*4 + ri];
            mnew[ri] = fmaxf(mold[ri], ml);
            float p[4]; float rs = 0.f;
#pragma unroll
            for (int cj = 0; cj < 4; cj++) {
                p[cj] = __expf(acc[ri][cj] - mnew[ri]);
                rs += p[cj];
            }
            rs += __shfl_xor_sync(0xffffffffu, rs, 8);
            rs += __shfl_xor_sync(0xffffffffu, rs, 4);
            rs += __shfl_xor_sync(0xffffffffu, rs, 2);
            rs += __shfl_xor_sync(0xffffffffu, rs, 1);
            rsum[ri] = rs;
            alv[ri]  = __expf(mold[ri] - mnew[ri]);
            *(float4*)&Ps[(ty*4 + ri)*68 + tx*4] = make_float4(p[0], p[1], p[2], p[3]);
        }
        __syncwarp();
        if (tx == 0) {
#pragma unroll
            for (int ri = 0; ri < 4; ri++) {
                int r = ty*4 + ri;
                mrow[r] = mnew[ri];
                lrow[r] = lrow[r]*alv[ri] + rsum[ri];
                arow[r] = alv[ri];
            }
        }
        __syncthreads();

        // rescale O, then O += P @ V
#pragma unroll
        for (int ri = 0; ri < 4; ri++) {
            float al = arow[ty*4 + ri];
#pragma unroll
            for (int q = 0; q < 4; q++)
#pragma unroll
                for (int cc = 0; cc < 4; cc++) O[ri][q][cc] *= al;
        }
#pragma unroll 2
        for (int j = 0; j < 64; j++) {
            float pr[4];
#pragma unroll
            for (int ri = 0; ri < 4; ri++) pr[ri] = Ps[(ty*4 + ri)*68 + j];
#pragma unroll
            for (int q = 0; q < 4; q++) {
                float vv[4];
                *(float4*)vv = *(const float4*)&Vs[j*260 + q*64 + tx*4];
#pragma unroll
                for (int ri = 0; ri < 4; ri++)
#pragma unroll
                    for (int cc = 0; cc < 4; cc++)
                        O[ri][q][cc] += pr[ri] * vv[cc];
            }
        }
        __syncthreads();
    }

    // normalize and write out[b][p][c]
#pragma unroll
    for (int ri = 0; ri < 4; ri++) {
        float inv = 1.0f / lrow[ty*4 + ri];
        int p = i0 + ty*4 + ri;
#pragma unroll
        for (int q = 0; q < 4; q++) {
            float4 o;
            o.x = O[ri][q][0]*inv; o.y = O[ri][q][1]*inv;
            o.z = O[ri][q][2]*inv; o.w = O[ri][q][3]*inv;
            *(float4*)&out[(b*NSP + p)*CH + q*64 + tx*4] = o;
        }
    }
}

// ---------------- launch ----------------
extern "C" void kernel_launch(void* const* d_in, const int* in_sizes, int n_in,
                              void* d_out, int out_size) {
    const float* x      = (const float*)d_in[0];
    const float* gamma  = (const float*)d_in[1];
    const float* beta   = (const float*)d_in[2];
    const float* w_qkv  = (const float*)d_in[3];
    const float* b_qkv  = (const float*)d_in[4];
    const float* w_proj = (const float*)d_in[5];
    const float* b_proj = (const float*)d_in[6];
    float* out = (float*)d_out;

    float *p_xn, *p_qkv, *p_vT, *p_attn;
    cudaGetSymbolAddress((void**)&p_xn,   g_xn);
    cudaGetSymbolAddress((void**)&p_qkv,  g_qkv);
    cudaGetSymbolAddress((void**)&p_vT,   g_vT);
    cudaGetSymbolAddress((void**)&p_attn, g_attn);

    // 1-2. GroupNorm
    gn_partial<<<BATCH*GROUPS*8, 256>>>(x);
    gn_apply<<<BATCH*CH*NSP/4/256, 256>>>(x, gamma, beta);

    // 3. QKV 1x1 conv: [768x256] x [256x4096] per batch
    gemm64<0><<<dim3(NSP/64, 3*CH/64, BATCH), 256>>>(
        w_qkv, p_xn, b_qkv, nullptr, p_qkv,
        3*CH, NSP, CH, CH*NSP, 3*CH*NSP, 0);

    // 4. V transpose -> [b][p][c]
    transposeV<<<dim3(NSP/32, CH/32, BATCH), dim3(32, 8)>>>(p_qkv, p_vT);

    // 5. flash attention -> g_attn [b][p][c]
    size_t smem = (size_t)(256*64*2 + 64*260 + 64*68 + 192) * sizeof(float);
    cudaFuncSetAttribute(flash64, cudaFuncAttributeMaxDynamicSharedMemorySize, (int)smem);
    flash64<<<dim3(NSP/64, BATCH), 256, smem>>>(p_qkv, p_vT, p_attn);

    // 6. proj + bias + residual -> out [b][c][h][w]
    gemm64<1><<<dim3(NSP/64, CH/64, BATCH), 256>>>(
        w_proj, p_attn, b_proj, x, out,
        CH, NSP, CH, NSP*CH, CH*NSP, CH*NSP);
}